// round 13
// baseline (speedup 1.0000x reference)
#include <cuda_runtime.h>
#include <cstddef>
#include <cstdint>

#define B_   2
#define N_   768
#define BN_  1536
#define D_   512
#define E_   64
#define LN_EPS 1e-5f
#define PADR 68            // kC smem row pitch (floats)
#define XP   130           // kB x-tile pitch (floats)
#define JT   8             // kC j-tiles per block

typedef unsigned long long ull;

// ---------------- scratch ----------------
__device__ float g_WR[D_ * E_];     // fused W_edges@W_rows, [d][f]
__device__ float g_WC[D_ * E_];     // fused W_edges@W_cols, [d][f]
__device__ float g_Rc[BN_ * E_];    // centered R'
__device__ float g_Cc[BN_ * E_];    // centered C'
__device__ float g_varR[BN_];
__device__ float g_varC[BN_];

// -------- f32x2 helpers --------
__device__ __forceinline__ void ffma2(ull& d, ull a, ull b) {
    asm("fma.rn.f32x2 %0, %1, %2, %0;" : "+l"(d) : "l"(a), "l"(b));
}
__device__ __forceinline__ ull pack2(float x) {
    ull r; unsigned u = __float_as_uint(x);
    asm("mov.b64 %0, {%1, %1};" : "=l"(r) : "r"(u));
    return r;
}

// ---------------- kernel A: K-split fused-weight build (measured 8.1us) -----
// task = (fh[5b], d2[8b], k8[3b]); thread computes 8-e partial of 2 f-outputs
// for a d-pair; butterfly-reduce over the 8 k8 lanes; lane k8==0 stores.
__global__ void __launch_bounds__(256) kA(const float* __restrict__ We,
                                          const float* __restrict__ Wr,
                                          const float* __restrict__ Wc) {
    int task = blockIdx.x * 256 + threadIdx.x;
    int k8 = task & 7;
    int d2 = (task >> 3) & 255;
    int fh = task >> 11;           // 0..31
    int f0 = fh, f1 = fh + 32;

    float2 ar0 = {0.f, 0.f}, ar1 = {0.f, 0.f};
    float2 ac0 = {0.f, 0.f}, ac1 = {0.f, 0.f};
    const float* we0p = We + f0 * E_ + k8 * 8;
    const float* we1p = We + f1 * E_ + k8 * 8;
#pragma unroll
    for (int e = 0; e < 8; e++) {
        int ge = k8 * 8 + e;
        float2 wr = *(const float2*)(Wr + (size_t)ge * D_ + d2 * 2);
        float2 wc = *(const float2*)(Wc + (size_t)ge * D_ + d2 * 2);
        float w0 = we0p[e], w1 = we1p[e];
        ar0.x = fmaf(w0, wr.x, ar0.x); ar0.y = fmaf(w0, wr.y, ar0.y);
        ar1.x = fmaf(w1, wr.x, ar1.x); ar1.y = fmaf(w1, wr.y, ar1.y);
        ac0.x = fmaf(w0, wc.x, ac0.x); ac0.y = fmaf(w0, wc.y, ac0.y);
        ac1.x = fmaf(w1, wc.x, ac1.x); ac1.y = fmaf(w1, wc.y, ac1.y);
    }
#pragma unroll
    for (int o = 4; o; o >>= 1) {
        ar0.x += __shfl_xor_sync(0xffffffffu, ar0.x, o);
        ar0.y += __shfl_xor_sync(0xffffffffu, ar0.y, o);
        ar1.x += __shfl_xor_sync(0xffffffffu, ar1.x, o);
        ar1.y += __shfl_xor_sync(0xffffffffu, ar1.y, o);
        ac0.x += __shfl_xor_sync(0xffffffffu, ac0.x, o);
        ac0.y += __shfl_xor_sync(0xffffffffu, ac0.y, o);
        ac1.x += __shfl_xor_sync(0xffffffffu, ac1.x, o);
        ac1.y += __shfl_xor_sync(0xffffffffu, ac1.y, o);
    }
    if (k8 == 0) {
        int d0 = d2 * 2;
        g_WR[(d0 + 0) * E_ + f0] = ar0.x;
        g_WR[(d0 + 1) * E_ + f0] = ar0.y;
        g_WR[(d0 + 0) * E_ + f1] = ar1.x;
        g_WR[(d0 + 1) * E_ + f1] = ar1.y;
        g_WC[(d0 + 0) * E_ + f0] = ac0.x;
        g_WC[(d0 + 1) * E_ + f0] = ac0.y;
        g_WC[(d0 + 0) * E_ + f1] = ac1.x;
        g_WC[(d0 + 1) * E_ + f1] = ac1.y;
    }
}

// ---------------- kernel B: row GEMM + center + variance (proven ~6us) ------
// grid 96, block 256, 16 rows/block. Reads pre-transposed hot g_WR/g_WC with
// contiguous float4; f32x2 FFMA inner loop; stats inline.
extern __shared__ float sm_b[];
__global__ void __launch_bounds__(256) kB(const float* __restrict__ x) {
    float* xs  = sm_b;            // 2080 floats
    float* wrs = sm_b + 2080;     // 8192
    float* wcs = wrs + 8192;      // 8192
    float* P   = sm_b + 2080;     // alias: 16384 floats

    int tid  = threadIdx.x;
    int f2   = tid & 31;
    int w    = tid >> 5;
    int row0 = blockIdx.x * 16;

    ull aR[16], aC[16];
#pragma unroll
    for (int r = 0; r < 16; r++) { aR[r] = 0ULL; aC[r] = 0ULL; }

    for (int c = 0; c < 4; c++) {
        int d0 = c * 128;
        for (int idx = tid; idx < 2048; idx += 256) {
            ((float4*)wrs)[idx] = ((const float4*)(g_WR + d0 * E_))[idx];
            ((float4*)wcs)[idx] = ((const float4*)(g_WC + d0 * E_))[idx];
        }
        for (int idx = tid; idx < 1024; idx += 256) {
            int r = idx >> 6, dd2 = idx & 63;
            *(float2*)(xs + r * XP + dd2 * 2) =
                *(const float2*)(x + (size_t)(row0 + r) * D_ + d0 + dd2 * 2);
        }
        __syncthreads();

        int wbase = w * 16;
#pragma unroll
        for (int p = 0; p < 8; p++) {
            int dd = wbase + p * 2;
            ull wr0 = *(const ull*)(wrs + dd * E_ + 2 * f2);
            ull wr1 = *(const ull*)(wrs + (dd + 1) * E_ + 2 * f2);
            ull wc0 = *(const ull*)(wcs + dd * E_ + 2 * f2);
            ull wc1 = *(const ull*)(wcs + (dd + 1) * E_ + 2 * f2);
#pragma unroll
            for (int r = 0; r < 16; r++) {
                float2 xv = *(const float2*)(xs + r * XP + dd);
                ull x0 = pack2(xv.x);
                ull x1 = pack2(xv.y);
                ffma2(aR[r], x0, wr0);
                ffma2(aR[r], x1, wr1);
                ffma2(aC[r], x0, wc0);
                ffma2(aC[r], x1, wc1);
            }
        }
        __syncthreads();
    }

#pragma unroll
    for (int r = 0; r < 16; r++) {
        *(ull*)(P + ((w * 2 + 0) * 16 + r) * E_ + 2 * f2) = aR[r];
        *(ull*)(P + ((w * 2 + 1) * 16 + r) * E_ + 2 * f2) = aC[r];
    }
    __syncthreads();

    int row = tid >> 4;
    int fq  = tid & 15;
    float4 R4 = make_float4(0.f, 0.f, 0.f, 0.f);
    float4 C4 = make_float4(0.f, 0.f, 0.f, 0.f);
#pragma unroll
    for (int ww = 0; ww < 8; ww++) {
        float4 pr = *(const float4*)(P + ((ww * 2 + 0) * 16 + row) * E_ + fq * 4);
        float4 pc = *(const float4*)(P + ((ww * 2 + 1) * 16 + row) * E_ + fq * 4);
        R4.x += pr.x; R4.y += pr.y; R4.z += pr.z; R4.w += pr.w;
        C4.x += pc.x; C4.y += pc.y; C4.z += pc.z; C4.w += pc.w;
    }
    float sR  = R4.x + R4.y + R4.z + R4.w;
    float sRR = R4.x * R4.x + R4.y * R4.y + R4.z * R4.z + R4.w * R4.w;
    float sC  = C4.x + C4.y + C4.z + C4.w;
    float sCC = C4.x * C4.x + C4.y * C4.y + C4.z * C4.z + C4.w * C4.w;
#pragma unroll
    for (int o = 1; o < 16; o <<= 1) {
        sR  += __shfl_xor_sync(0xffffffffu, sR,  o);
        sRR += __shfl_xor_sync(0xffffffffu, sRR, o);
        sC  += __shfl_xor_sync(0xffffffffu, sC,  o);
        sCC += __shfl_xor_sync(0xffffffffu, sCC, o);
    }
    float mR = sR * (1.f / 64.f);
    float mC = sC * (1.f / 64.f);
    int grow = row0 + row;
    float4 oR = make_float4(R4.x - mR, R4.y - mR, R4.z - mR, R4.w - mR);
    float4 oC = make_float4(C4.x - mC, C4.y - mC, C4.z - mC, C4.w - mC);
    *(float4*)(g_Rc + grow * E_ + fq * 4) = oR;
    *(float4*)(g_Cc + grow * E_ + fq * 4) = oC;
    if (fq == 0) {
        g_varR[grow] = sRR * (1.f / 64.f) - mR * mR;
        g_varC[grow] = sCC * (1.f / 64.f) - mC * mC;
    }
}

// ---------------- kernel C: R8 pipelined epilogue (EXACT, measured 52.4us) ---
__global__ void __launch_bounds__(256, 4) kC(const float* __restrict__ gamma,
                                             const float* __restrict__ beta,
                                             float* __restrict__ out) {
    __shared__ float rs[16 * PADR];
    __shared__ float cs[2][16 * PADR];
    __shared__ float vR[16];
    __shared__ float vC[2][16];
    __shared__ float inv[256];

    int i0 = blockIdx.x * 16;
    int b  = blockIdx.y;
    int jg = blockIdx.z;
    int tid = threadIdx.x;
    int rowR = b * N_ + i0;
    int rw = tid >> 4;
    int f4 = tid & 15;

    ((float4*)(rs + rw * PADR))[f4] = ((const float4*)(g_Rc + (size_t)(rowR + rw) * E_))[f4];
    if (tid < 16) vR[tid] = g_varR[rowR + tid];
    {
        int rowC = b * N_ + jg * JT * 16;
        ((float4*)(cs[0] + rw * PADR))[f4] = ((const float4*)(g_Cc + (size_t)(rowC + rw) * E_))[f4];
        if (tid < 16) vC[0][tid] = g_varC[rowC + tid];
    }
    __syncthreads();

    float4 gm = __ldg((const float4*)gamma + f4);
    float4 bt = __ldg((const float4*)beta + f4);
    float4 rr = ((const float4*)(rs + rw * PADR))[f4];
    float4 u;
    u.x = rr.x * gm.x; u.y = rr.y * gm.y; u.z = rr.z * gm.z; u.w = rr.w * gm.w;

    for (int t = 0; t < JT; t++) {
        int cur = t & 1, nxt = cur ^ 1;
        float* csc = cs[cur];

        float4 pc;
        float pv = 0.f;
        if (t + 1 < JT) {
            int rowCn = b * N_ + (jg * JT + t + 1) * 16;
            pc = ((const float4*)(g_Cc + (size_t)(rowCn + rw) * E_))[f4];
            if (tid < 16) pv = g_varC[rowCn + tid];
        }

        {
            int ii = tid >> 4, jj = tid & 15;
            const float4* r4 = (const float4*)(rs + ii * PADR);
            const float4* c4 = (const float4*)(csc + jj * PADR);
            float d = 0.f;
#pragma unroll
            for (int k = 0; k < 16; k++) {
                float4 a = r4[k], c = c4[k];
                d = fmaf(a.x, c.x, d);
                d = fmaf(a.y, c.y, d);
                d = fmaf(a.z, c.z, d);
                d = fmaf(a.w, c.w, d);
            }
            float var = vR[ii] + vC[cur][jj] + d * (2.f / 64.f);
            inv[tid] = rsqrtf(var + LN_EPS);
        }
        __syncthreads();

        const float* invg = inv + rw * 16;
        const float4* ivp = (const float4*)invg;
        float4 iva = ivp[0], ivb = ivp[1], ivc = ivp[2], ivd = ivp[3];
        float ivs[16] = {iva.x, iva.y, iva.z, iva.w, ivb.x, ivb.y, ivb.z, ivb.w,
                         ivc.x, ivc.y, ivc.z, ivc.w, ivd.x, ivd.y, ivd.z, ivd.w};
        float4* op = (float4*)out +
                     ((size_t)(b * N_ + i0 + rw) * N_ + (jg * JT + t) * 16) * 16 + f4;
#pragma unroll
        for (int jj = 0; jj < 16; jj++) {
            float4 c = ((const float4*)(csc + jj * PADR))[f4];
            float iv = ivs[jj];
            float4 o;
            o.x = fmaf(fmaf(c.x, gm.x, u.x), iv, bt.x);
            o.y = fmaf(fmaf(c.y, gm.y, u.y), iv, bt.y);
            o.z = fmaf(fmaf(c.z, gm.z, u.z), iv, bt.z);
            o.w = fmaf(fmaf(c.w, gm.w, u.w), iv, bt.w);
            __stcs(op + (size_t)jj * 16, o);
        }

        if (t + 1 < JT) {
            ((float4*)(cs[nxt] + rw * PADR))[f4] = pc;
            if (tid < 16) vC[nxt][tid] = pv;
        }
        __syncthreads();
    }
}

// ---------------- launch -------------------------------------------------------
#define KB_SMEM ((2080 + 8192 + 8192) * 4)

extern "C" void kernel_launch(void* const* d_in, const int* in_sizes, int n_in,
                              void* d_out, int out_size) {
    const float* x     = (const float*)d_in[0];  // [2,768,512]
    const float* Wr    = (const float*)d_in[1];  // [64,512]
    const float* Wc    = (const float*)d_in[2];  // [64,512]
    const float* We    = (const float*)d_in[3];  // [64,64]
    const float* gamma = (const float*)d_in[4];  // [64]
    const float* beta  = (const float*)d_in[5];  // [64]
    float* out = (float*)d_out;                  // [2,768,768,64] fp32

    static int smem_set = 0;
    if (!smem_set) {
        cudaFuncSetAttribute(kB, cudaFuncAttributeMaxDynamicSharedMemorySize, KB_SMEM);
        smem_set = 1;
    }

    kA<<<256, 256>>>(We, Wr, Wc);
    kB<<<96, 256, KB_SMEM>>>(x);
    kC<<<dim3(N_ / 16, B_, N_ / 16 / JT), 256>>>(gamma, beta, out);
}